// round 7
// baseline (speedup 1.0000x reference)
#include <cuda_runtime.h>
#include <cuda.h>
#include <math.h>
#include <stdint.h>

#define M_TOTAL 25088   // 128*14*14
#define K_DIM   512
#define N_DIM   2048
#define KXB     1024    // bytes per row: 8 segments x [u1(64B) | u2(64B)]

#define BM 128
#define BN 128
#define STAGES 3
#define NT 8                         // 8 segments of K=64 (both slices together)
#define A_TILE_BYTES (BM * 128)      // 16384
#define B_TILE_BYTES (BN * 128)      // 16384
#define STAGE_BYTES (A_TILE_BYTES + B_TILE_BYTES)  // 32768
#define SMEM_DYN (STAGES * STAGE_BYTES + 1024)

// int8 slice scratch + per-row dequant scales (allocation-free device globals)
__device__ uint8_t g_A[(size_t)M_TOTAL * KXB];
__device__ uint8_t g_B[(size_t)N_DIM * KXB];
__device__ float   g_sA[M_TOTAL];
__device__ float   g_sB[N_DIM];

// ---------------------------------------------------------------------------
// PTX helpers (sm_90-baseline features only)
// ---------------------------------------------------------------------------
__device__ __forceinline__ uint32_t smem_u32(const void* p) {
    uint32_t a;
    asm("{ .reg .u64 t; cvta.to.shared.u64 t, %1; cvt.u32.u64 %0, t; }" : "=r"(a) : "l"(p));
    return a;
}

#define MBARRIER_INIT(addr, cnt) \
    asm volatile("mbarrier.init.shared.b64 [%0], %1;" :: "r"(addr), "r"(cnt) : "memory")

#define MBARRIER_EXPECT_TX(addr, bytes) \
    asm volatile("mbarrier.arrive.expect_tx.shared.b64 _, [%0], %1;" :: "r"(addr), "r"(bytes) : "memory")

#define MBARRIER_WAIT_PARITY(addr, parity) do {                                   \
    uint32_t _mbar = (uint32_t)(addr);                                            \
    uint32_t _par  = (uint32_t)(parity);                                          \
    uint32_t _done;                                                               \
    asm volatile(                                                                 \
        "{\n\t.reg .pred p;\n\t"                                                  \
        "mbarrier.try_wait.parity.acquire.cta.shared::cta.b64 p, [%1], %2;\n\t"   \
        "selp.b32 %0, 1, 0, p;\n\t}"                                              \
        : "=r"(_done) : "r"(_mbar), "r"(_par) : "memory");                        \
    if (!_done) {                                                                 \
        asm volatile(                                                             \
            "{\n\t.reg .pred P1;\n\t"                                             \
            "WAIT_LOOP_%=:\n\t"                                                   \
            "mbarrier.try_wait.parity.acquire.cta.shared::cta.b64 P1, [%0], %1, 0x989680;\n\t" \
            "@P1 bra.uni WAIT_DONE_%=;\n\t"                                       \
            "bra.uni WAIT_LOOP_%=;\n\t"                                           \
            "WAIT_DONE_%=:\n\t}"                                                  \
            :: "r"(_mbar), "r"(_par) : "memory");                                 \
    }                                                                             \
} while (0)

#define TMA_LOAD_3D(smem_addr, tmap, cx, cy, cz, mbar)                            \
    asm volatile(                                                                 \
        "cp.async.bulk.tensor.3d.shared::cta.global.tile.mbarrier::complete_tx::bytes " \
        "[%0], [%1, {%2, %3, %4}], [%5];"                                         \
        :: "r"((uint32_t)(smem_addr)), "l"(tmap), "r"((int32_t)(cx)),             \
           "r"((int32_t)(cy)), "r"((int32_t)(cz)), "r"((uint32_t)(mbar))          \
        : "memory")

#define LDSM_X4(r, addr) \
    asm volatile("ldmatrix.sync.aligned.m8n8.x4.shared.b16 {%0,%1,%2,%3}, [%4];" \
        : "=r"((r)[0]), "=r"((r)[1]), "=r"((r)[2]), "=r"((r)[3]) : "r"(addr))

__device__ __forceinline__ void mma_s8(int* d, const uint32_t* a, const uint32_t* b) {
    asm volatile(
        "mma.sync.aligned.m16n8k32.row.col.s32.s8.s8.s32 "
        "{%0,%1,%2,%3}, {%4,%5,%6,%7}, {%8,%9}, {%0,%1,%2,%3};"
        : "+r"(d[0]), "+r"(d[1]), "+r"(d[2]), "+r"(d[3])
        : "r"(a[0]), "r"(a[1]), "r"(a[2]), "r"(a[3]), "r"(b[0]), "r"(b[1]));
}

__device__ __forceinline__ uint32_t pack4(int a, int b, int c, int d) {
    return (uint32_t)(a & 0xFF) | ((uint32_t)(b & 0xFF) << 8) |
           ((uint32_t)(c & 0xFF) << 16) | ((uint32_t)(d & 0xFF) << 24);
}

// quantize 4 floats -> u1 (7-bit) + u2 (6-bit residual) packed words
__device__ __forceinline__ void quant4(const float* v, float inv, uint32_t& p1, uint32_t& p2) {
    int i1[4], i2[4];
    #pragma unroll
    for (int j = 0; j < 4; j++) {
        float q = v[j] * inv;
        i1[j] = __float2int_rn(q);
        float e = q - (float)i1[j];
        i2[j] = __float2int_rn(e * 126.0f);
    }
    p1 = pack4(i1[0], i1[1], i1[2], i1[3]);
    p2 = pack4(i2[0], i2[1], i2[2], i2[3]);
}

// ---------------------------------------------------------------------------
// Kernel 1 (merged): LN + int8-quantize x -> g_A; quantize W -> g_B.
// Row layout (1024B): segment s (64 orig cols): [u1 x64 | u2 x64]
// ---------------------------------------------------------------------------
__global__ void __launch_bounds__(128) convert_kernel(
    const float* __restrict__ x,
    const float* __restrict__ gamma,
    const float* __restrict__ beta,
    const float* __restrict__ W)
{
    const int blk = blockIdx.x;
    const int tid = threadIdx.x;

    const int j0  = tid * 4;
    const int seg = j0 >> 6;
    const int w   = j0 & 63;

    __shared__ float sm4[4];
    __shared__ float sbc[2];   // [0] = mean or amax, [1] = rstd

    float vals[4];

    if (blk < M_TOTAL) {
        const int row = blk;
        float4 v = reinterpret_cast<const float4*>(x + (size_t)row * K_DIM)[tid];
        float s  = v.x + v.y + v.z + v.w;
        float sq = fmaf(v.x, v.x, fmaf(v.y, v.y, fmaf(v.z, v.z, v.w * v.w)));
        #pragma unroll
        for (int o = 16; o > 0; o >>= 1) {
            s  += __shfl_xor_sync(0xffffffff, s,  o);
            sq += __shfl_xor_sync(0xffffffff, sq, o);
        }
        __shared__ float ssq[4];
        const int wi = tid >> 5, l = tid & 31;
        if (l == 0) { sm4[wi] = s; ssq[wi] = sq; }
        __syncthreads();
        if (tid == 0) {
            float S = sm4[0] + sm4[1] + sm4[2] + sm4[3];
            float SQ = ssq[0] + ssq[1] + ssq[2] + ssq[3];
            float mean = S * (1.0f / K_DIM);
            float var  = SQ * (1.0f / K_DIM) - mean * mean;
            sbc[0] = mean; sbc[1] = rsqrtf(var + 1e-6f);
        }
        __syncthreads();
        const float mean = sbc[0], rstd = sbc[1];

        float4 g  = reinterpret_cast<const float4*>(gamma)[tid];
        float4 be = reinterpret_cast<const float4*>(beta)[tid];
        vals[0] = (v.x - mean) * rstd * g.x + be.x;
        vals[1] = (v.y - mean) * rstd * g.y + be.y;
        vals[2] = (v.z - mean) * rstd * g.z + be.z;
        vals[3] = (v.w - mean) * rstd * g.w + be.w;
    } else {
        const int row = blk - M_TOTAL;
        float4 v = reinterpret_cast<const float4*>(W + (size_t)row * K_DIM)[tid];
        vals[0] = v.x; vals[1] = v.y; vals[2] = v.z; vals[3] = v.w;
    }

    // block-wide amax
    float am = fmaxf(fmaxf(fabsf(vals[0]), fabsf(vals[1])),
                     fmaxf(fabsf(vals[2]), fabsf(vals[3])));
    #pragma unroll
    for (int o = 16; o > 0; o >>= 1)
        am = fmaxf(am, __shfl_xor_sync(0xffffffff, am, o));
    __syncthreads();            // sm4 reuse guard
    const int wi = tid >> 5, l = tid & 31;
    if (l == 0) sm4[wi] = am;
    __syncthreads();
    if (tid == 0)
        sbc[0] = fmaxf(fmaxf(fmaxf(sm4[0], sm4[1]), fmaxf(sm4[2], sm4[3])), 1e-20f);
    __syncthreads();
    const float amax = sbc[0];
    const float inv = 127.0f / amax;

    uint32_t p1, p2;
    quant4(vals, inv, p1, p2);

    if (blk < M_TOTAL) {
        uint8_t* base = g_A + (size_t)blk * KXB + seg * 128 + w;
        *reinterpret_cast<uint32_t*>(base)      = p1;
        *reinterpret_cast<uint32_t*>(base + 64) = p2;
        if (tid == 0) g_sA[blk] = amax * (1.0f / 127.0f);
    } else {
        const int row = blk - M_TOTAL;
        uint8_t* base = g_B + (size_t)row * KXB + seg * 128 + w;
        *reinterpret_cast<uint32_t*>(base)      = p1;
        *reinterpret_cast<uint32_t*>(base + 64) = p2;
        if (tid == 0) g_sB[row] = amax * (1.0f / 127.0f);
    }
}

// ---------------------------------------------------------------------------
// Kernel 2: TMA-pipelined s8 IMMA GEMM (2-slice Ozaki, 3 terms) + dequant
//           + bias + exact GELU
// ---------------------------------------------------------------------------
__device__ __forceinline__ void issue_tile_load(
    int kt, int s, uint32_t tiles_base, uint32_t mbar,
    const CUtensorMap* mapA, const CUtensorMap* mapB, int bm, int bn)
{
    const uint32_t a_dst = tiles_base + s * STAGE_BYTES;
    const uint32_t b_dst = a_dst + A_TILE_BYTES;
    MBARRIER_EXPECT_TX(mbar, STAGE_BYTES);
    TMA_LOAD_3D(a_dst, mapA, kt * 128, bm, 0, mbar);
    TMA_LOAD_3D(b_dst, mapB, kt * 128, bn, 0, mbar);
}

__global__ void __launch_bounds__(256, 1) gemm_kernel(
    const __grid_constant__ CUtensorMap tma_a,
    const __grid_constant__ CUtensorMap tma_b,
    const float* __restrict__ bias,
    float* __restrict__ out)
{
    extern __shared__ char dynsmem[];
    __shared__ __align__(8) uint64_t mbar_full[STAGES];

    const int tid  = threadIdx.x;
    const int wid  = tid >> 5;
    const int lane = tid & 31;
    const int bm = blockIdx.y * BM;
    const int bn = blockIdx.x * BN;

    const int wm = (wid >> 2) * 64;   // warp m offset (0 or 64)
    const int wn = (wid & 3) * 32;    // warp n offset (0,32,64,96)

    const uint32_t tiles_base = (smem_u32(dynsmem) + 1023u) & ~1023u;

    if (tid == 0) {
        #pragma unroll
        for (int s = 0; s < STAGES; s++)
            MBARRIER_INIT(smem_u32(&mbar_full[s]), 1);
    }
    __syncthreads();

    if (tid == 0) {
        #pragma unroll
        for (int s = 0; s < STAGES; s++)
            issue_tile_load(s, s, tiles_base, smem_u32(&mbar_full[s]), &tma_a, &tma_b, bm, bn);
    }

    // --- per-lane ldmatrix address components (SW128 swizzle, 128B rows) ---
    // identical math to the bf16 version: b16-tile bytes == s8 fragment bytes
    const int a_row = wm + ((lane >> 3) & 1) * 8 + (lane & 7);
    const uint32_t a_row_off = (uint32_t)a_row * 128u;
    const uint32_t a_xor = (uint32_t)(a_row & 7) * 16u;
    const uint32_t a_kb = (uint32_t)(lane >> 4) * 16u;
    const int b_row = wn + (lane >> 4) * 8 + (lane & 7);
    const uint32_t b_row_off = (uint32_t)b_row * 128u;
    const uint32_t b_xor = (uint32_t)(b_row & 7) * 16u;
    const uint32_t b_kb = (uint32_t)((lane >> 3) & 1) * 16u;

    int acc1[4][4][4];   // sum u1*w1
    int accX[4][4][4];   // sum (u1*w2 + u2*w1)
    #pragma unroll
    for (int i = 0; i < 4; i++)
        #pragma unroll
        for (int j = 0; j < 4; j++)
            #pragma unroll
            for (int q = 0; q < 4; q++) { acc1[i][j][q] = 0; accX[i][j][q] = 0; }

    for (int kt = 0; kt < NT; kt++) {
        const int s = kt % STAGES;
        const int par = (kt / STAGES) & 1;
        MBARRIER_WAIT_PARITY(smem_u32(&mbar_full[s]), par);

        const uint32_t a_base = tiles_base + s * STAGE_BYTES + a_row_off;
        const uint32_t b_base = tiles_base + s * STAGE_BYTES + A_TILE_BYTES + b_row_off;

        // 128B row: u1 bytes [0,64), u2 bytes [64,128); ks picks 32B (k=32 int8)
        #pragma unroll
        for (int ks = 0; ks < 2; ks++) {
            const uint32_t akh = (uint32_t)ks * 32u + a_kb;          // A u1
            const uint32_t akl = akh + 64u;                          // A u2
            const uint32_t bkh = (uint32_t)ks * 32u + b_kb;          // B w1
            const uint32_t bkl = bkh + 64u;                          // B w2

            uint32_t ah[4][4], bh[2][4], bl[2][4];
            #pragma unroll
            for (int mt = 0; mt < 4; mt++)
                LDSM_X4(ah[mt], a_base + (uint32_t)mt * 2048u + (akh ^ a_xor));
            #pragma unroll
            for (int np = 0; np < 2; np++) {
                LDSM_X4(bh[np], b_base + (uint32_t)np * 2048u + (bkh ^ b_xor));
                LDSM_X4(bl[np], b_base + (uint32_t)np * 2048u + (bkl ^ b_xor));
            }

            if (ks == 1) {
                uint32_t al[4][4];
                #pragma unroll
                for (int mt = 0; mt < 4; mt++)
                    LDSM_X4(al[mt], a_base + (uint32_t)mt * 2048u + (akl ^ a_xor));

                __syncthreads();   // all smem reads of stage s done -> refill
                if (tid == 0 && kt + STAGES < NT)
                    issue_tile_load(kt + STAGES, s, tiles_base, smem_u32(&mbar_full[s]),
                                    &tma_a, &tma_b, bm, bn);

                #pragma unroll
                for (int mt = 0; mt < 4; mt++)
                    #pragma unroll
                    for (int nt = 0; nt < 4; nt++)
                        mma_s8(acc1[mt][nt], ah[mt], &bh[nt >> 1][(nt & 1) * 2]);
                #pragma unroll
                for (int mt = 0; mt < 4; mt++)
                    #pragma unroll
                    for (int nt = 0; nt < 4; nt++)
                        mma_s8(accX[mt][nt], ah[mt], &bl[nt >> 1][(nt & 1) * 2]);
                #pragma unroll
                for (int mt = 0; mt < 4; mt++)
                    #pragma unroll
                    for (int nt = 0; nt < 4; nt++)
                        mma_s8(accX[mt][nt], al[mt], &bh[nt >> 1][(nt & 1) * 2]);
            } else {
                uint32_t al[4][4];
                #pragma unroll
                for (int mt = 0; mt < 4; mt++)
                    LDSM_X4(al[mt], a_base + (uint32_t)mt * 2048u + (akl ^ a_xor));
                #pragma unroll
                for (int mt = 0; mt < 4; mt++)
                    #pragma unroll
                    for (int nt = 0; nt < 4; nt++)
                        mma_s8(acc1[mt][nt], ah[mt], &bh[nt >> 1][(nt & 1) * 2]);
                #pragma unroll
                for (int mt = 0; mt < 4; mt++)
                    #pragma unroll
                    for (int nt = 0; nt < 4; nt++)
                        mma_s8(accX[mt][nt], ah[mt], &bl[nt >> 1][(nt & 1) * 2]);
                #pragma unroll
                for (int mt = 0; mt < 4; mt++)
                    #pragma unroll
                    for (int nt = 0; nt < 4; nt++)
                        mma_s8(accX[mt][nt], al[mt], &bh[nt >> 1][(nt & 1) * 2]);
            }
        }
    }

    // --- epilogue: dequant + bias + exact GELU, float2 stores ---
    const int gr = lane >> 2;
    const int gc = (lane & 3) * 2;

    float sa0[4], sa1[4];
    #pragma unroll
    for (int mt = 0; mt < 4; mt++) {
        const int m0 = bm + wm + mt * 16 + gr;
        sa0[mt] = __ldg(&g_sA[m0]);
        sa1[mt] = __ldg(&g_sA[m0 + 8]);
    }

    #pragma unroll
    for (int nt = 0; nt < 4; nt++) {
        const int n = bn + wn + nt * 8 + gc;
        const float2 b2 = __ldg(reinterpret_cast<const float2*>(bias + n));
        const float sb0 = __ldg(&g_sB[n]);
        const float sb1 = __ldg(&g_sB[n + 1]);
        #pragma unroll
        for (int mt = 0; mt < 4; mt++) {
            const int m0 = bm + wm + mt * 16 + gr;
            const float d00 = sa0[mt] * sb0, d01 = sa0[mt] * sb1;
            const float d10 = sa1[mt] * sb0, d11 = sa1[mt] * sb1;
            float v0 = fmaf((float)acc1[mt][nt][0] + (float)accX[mt][nt][0] * (1.0f/126.0f), d00, b2.x);
            float v1 = fmaf((float)acc1[mt][nt][1] + (float)accX[mt][nt][1] * (1.0f/126.0f), d01, b2.y);
            float v2 = fmaf((float)acc1[mt][nt][2] + (float)accX[mt][nt][2] * (1.0f/126.0f), d10, b2.x);
            float v3 = fmaf((float)acc1[mt][nt][3] + (float)accX[mt][nt][3] * (1.0f/126.0f), d11, b2.y);
            float2 o0, o1;
            o0.x = 0.5f * v0 * (1.0f + erff(v0 * 0.70710678118654752f));
            o0.y = 0.5f * v1 * (1.0f + erff(v1 * 0.70710678118654752f));
            o1.x = 0.5f * v2 * (1.0f + erff(v2 * 0.70710678118654752f));
            o1.y = 0.5f * v3 * (1.0f + erff(v3 * 0.70710678118654752f));
            *reinterpret_cast<float2*>(out + (size_t)m0 * N_DIM + n) = o0;
            *reinterpret_cast<float2*>(out + (size_t)(m0 + 8) * N_DIM + n) = o1;
        }
    }
}

// ---------------------------------------------------------------------------
// Host side
// ---------------------------------------------------------------------------
typedef CUresult (*EncodeFn)(CUtensorMap*, CUtensorMapDataType, cuuint32_t, void*,
                             const cuuint64_t*, const cuuint64_t*, const cuuint32_t*,
                             const cuuint32_t*, CUtensorMapInterleave, CUtensorMapSwizzle,
                             CUtensorMapL2promotion, CUtensorMapFloatOOBfill);

static void encode_map(EncodeFn enc, CUtensorMap* map, void* base, uint64_t rows) {
    uint64_t dims[3]    = {KXB, rows, 1};
    uint64_t strides[2] = {KXB, rows * KXB};
    uint32_t box[3]     = {128, 128, 1};
    uint32_t estr[3]    = {1, 1, 1};
    enc(map, CU_TENSOR_MAP_DATA_TYPE_UINT8, 3, base, dims, strides, box, estr,
        CU_TENSOR_MAP_INTERLEAVE_NONE, CU_TENSOR_MAP_SWIZZLE_128B,
        CU_TENSOR_MAP_L2_PROMOTION_L2_128B, CU_TENSOR_MAP_FLOAT_OOB_FILL_NONE);
}

extern "C" void kernel_launch(void* const* d_in, const int* in_sizes, int n_in,
                              void* d_out, int out_size) {
    const float* x     = (const float*)d_in[0];
    const float* gamma = (const float*)d_in[1];
    const float* beta  = (const float*)d_in[2];
    const float* W     = (const float*)d_in[3];
    const float* b     = (const float*)d_in[4];
    float* out = (float*)d_out;

    void* pA = nullptr; void* pB = nullptr;
    cudaGetSymbolAddress(&pA, g_A);
    cudaGetSymbolAddress(&pB, g_B);

    EncodeFn enc = nullptr;
    cudaDriverEntryPointQueryResult qres;
    cudaGetDriverEntryPoint("cuTensorMapEncodeTiled", (void**)&enc, cudaEnableDefault, &qres);

    CUtensorMap mapA, mapB;
    encode_map(enc, &mapA, pA, M_TOTAL);
    encode_map(enc, &mapB, pB, N_DIM);

    convert_kernel<<<M_TOTAL + N_DIM, 128>>>(x, gamma, beta, W);

    cudaFuncSetAttribute(gemm_kernel, cudaFuncAttributeMaxDynamicSharedMemorySize, SMEM_DYN);
    dim3 grid(N_DIM / BN, M_TOTAL / BM);   // (16, 196)
    gemm_kernel<<<grid, 256, SMEM_DYN>>>(mapA, mapB, b, out);
}

// round 8
// speedup vs baseline: 3.1872x; 3.1872x over previous
#include <cuda_runtime.h>
#include <cuda.h>
#include <cuda_bf16.h>
#include <math.h>
#include <stdint.h>

#define M_TOTAL 25088   // 128*14*14
#define K_DIM   512
#define N_DIM   2048
#define KX      1024    // interleaved: 16 chunks of [hi(32)|lo(32)]

#define BM 128
#define BN 128
#define STAGES 3
#define CPT 16                       // chunks per tile (K=32 orig each)
#define A_TILE_BYTES (BM * 128)      // 16384
#define B_TILE_BYTES (BN * 128)      // 16384
#define STAGE_BYTES (A_TILE_BYTES + B_TILE_BYTES)  // 32768
#define SMEM_DYN (STAGES * STAGE_BYTES + 1024)

#define GRID_P 304                   // persistent CTAs (2 per SM x 152)
#define NTILES 3136                  // (25088/128) * (2048/128)

// bf16 hi/lo scratch (allocation-free device globals)
__device__ __nv_bfloat16 g_A[(size_t)M_TOTAL * KX];
__device__ __nv_bfloat16 g_B[(size_t)N_DIM * KX];

// ---------------------------------------------------------------------------
// PTX helpers (sm_90-baseline features only)
// ---------------------------------------------------------------------------
__device__ __forceinline__ uint32_t smem_u32(const void* p) {
    uint32_t a;
    asm("{ .reg .u64 t; cvta.to.shared.u64 t, %1; cvt.u32.u64 %0, t; }" : "=r"(a) : "l"(p));
    return a;
}

#define MBARRIER_INIT(addr, cnt) \
    asm volatile("mbarrier.init.shared.b64 [%0], %1;" :: "r"(addr), "r"(cnt) : "memory")

#define MBARRIER_EXPECT_TX(addr, bytes) \
    asm volatile("mbarrier.arrive.expect_tx.shared.b64 _, [%0], %1;" :: "r"(addr), "r"(bytes) : "memory")

#define MBARRIER_WAIT_PARITY(addr, parity) do {                                   \
    uint32_t _mbar = (uint32_t)(addr);                                            \
    uint32_t _par  = (uint32_t)(parity);                                          \
    uint32_t _done;                                                               \
    asm volatile(                                                                 \
        "{\n\t.reg .pred p;\n\t"                                                  \
        "mbarrier.try_wait.parity.acquire.cta.shared::cta.b64 p, [%1], %2;\n\t"   \
        "selp.b32 %0, 1, 0, p;\n\t}"                                              \
        : "=r"(_done) : "r"(_mbar), "r"(_par) : "memory");                        \
    if (!_done) {                                                                 \
        asm volatile(                                                             \
            "{\n\t.reg .pred P1;\n\t"                                             \
            "WAIT_LOOP_%=:\n\t"                                                   \
            "mbarrier.try_wait.parity.acquire.cta.shared::cta.b64 P1, [%0], %1, 0x989680;\n\t" \
            "@P1 bra.uni WAIT_DONE_%=;\n\t"                                       \
            "bra.uni WAIT_LOOP_%=;\n\t"                                           \
            "WAIT_DONE_%=:\n\t}"                                                  \
            :: "r"(_mbar), "r"(_par) : "memory");                                 \
    }                                                                             \
} while (0)

#define TMA_LOAD_3D(smem_addr, tmap, cx, cy, cz, mbar)                            \
    asm volatile(                                                                 \
        "cp.async.bulk.tensor.3d.shared::cta.global.tile.mbarrier::complete_tx::bytes " \
        "[%0], [%1, {%2, %3, %4}], [%5];"                                         \
        :: "r"((uint32_t)(smem_addr)), "l"(tmap), "r"((int32_t)(cx)),             \
           "r"((int32_t)(cy)), "r"((int32_t)(cz)), "r"((uint32_t)(mbar))          \
        : "memory")

#define LDSM_X4(r, addr) \
    asm volatile("ldmatrix.sync.aligned.m8n8.x4.shared.b16 {%0,%1,%2,%3}, [%4];" \
        : "=r"((r)[0]), "=r"((r)[1]), "=r"((r)[2]), "=r"((r)[3]) : "r"(addr))

__device__ __forceinline__ void mma16816(float* d, const uint32_t* a, const uint32_t* b) {
    asm volatile(
        "mma.sync.aligned.m16n8k16.row.col.f32.bf16.bf16.f32 "
        "{%0,%1,%2,%3}, {%4,%5,%6,%7}, {%8,%9}, {%0,%1,%2,%3};"
        : "+f"(d[0]), "+f"(d[1]), "+f"(d[2]), "+f"(d[3])
        : "r"(a[0]), "r"(a[1]), "r"(a[2]), "r"(a[3]), "r"(b[0]), "r"(b[1]));
}

__device__ __forceinline__ void split_bf16(float v, __nv_bfloat16& hi, __nv_bfloat16& lo) {
    hi = __float2bfloat16(v);
    lo = __float2bfloat16(v - __bfloat162float(hi));
}

// ---------------------------------------------------------------------------
// Kernel 1 (merged): LN+split x -> g_A, and split W -> g_B.
// Interleaved layout: chunk c (32 orig cols): dest [64c,64c+32)=hi, [64c+32,64c+64)=lo
// ---------------------------------------------------------------------------
__global__ void __launch_bounds__(128) convert_kernel(
    const float* __restrict__ x,
    const float* __restrict__ gamma,
    const float* __restrict__ beta,
    const float* __restrict__ W)
{
    const int blk = blockIdx.x;
    const int tid = threadIdx.x;

    const int j0 = tid * 4;
    const int c  = j0 >> 5;
    const int w  = j0 & 31;

    if (blk < M_TOTAL) {
        const int row = blk;
        float4 v = reinterpret_cast<const float4*>(x + (size_t)row * K_DIM)[tid];
        float s  = v.x + v.y + v.z + v.w;
        float sq = fmaf(v.x, v.x, fmaf(v.y, v.y, fmaf(v.z, v.z, v.w * v.w)));
        #pragma unroll
        for (int o = 16; o > 0; o >>= 1) {
            s  += __shfl_xor_sync(0xffffffff, s,  o);
            sq += __shfl_xor_sync(0xffffffff, sq, o);
        }
        __shared__ float ss[4], ssq[4];
        __shared__ float2 st;
        const int wi = tid >> 5, l = tid & 31;
        if (l == 0) { ss[wi] = s; ssq[wi] = sq; }
        __syncthreads();
        if (tid == 0) {
            float S = ss[0] + ss[1] + ss[2] + ss[3];
            float SQ = ssq[0] + ssq[1] + ssq[2] + ssq[3];
            float mean = S * (1.0f / K_DIM);
            float var  = SQ * (1.0f / K_DIM) - mean * mean;
            st = make_float2(mean, rsqrtf(var + 1e-6f));
        }
        __syncthreads();
        const float mean = st.x, rstd = st.y;

        float4 g  = reinterpret_cast<const float4*>(gamma)[tid];
        float4 be = reinterpret_cast<const float4*>(beta)[tid];
        float xn0 = (v.x - mean) * rstd * g.x + be.x;
        float xn1 = (v.y - mean) * rstd * g.y + be.y;
        float xn2 = (v.z - mean) * rstd * g.z + be.z;
        float xn3 = (v.w - mean) * rstd * g.w + be.w;

        __nv_bfloat16 h0, h1, h2, h3, l0, l1, l2, l3;
        split_bf16(xn0, h0, l0); split_bf16(xn1, h1, l1);
        split_bf16(xn2, h2, l2); split_bf16(xn3, h3, l3);

        __nv_bfloat16* base = g_A + (size_t)row * KX + c * 64 + w;
        __nv_bfloat162* hd = reinterpret_cast<__nv_bfloat162*>(base);
        __nv_bfloat162* ld = reinterpret_cast<__nv_bfloat162*>(base + 32);
        hd[0] = __nv_bfloat162(h0, h1); hd[1] = __nv_bfloat162(h2, h3);
        ld[0] = __nv_bfloat162(l0, l1); ld[1] = __nv_bfloat162(l2, l3);
    } else {
        const int row = blk - M_TOTAL;
        float4 v = reinterpret_cast<const float4*>(W + (size_t)row * K_DIM)[tid];
        __nv_bfloat16 h0, h1, h2, h3, l0, l1, l2, l3;
        split_bf16(v.x, h0, l0); split_bf16(v.y, h1, l1);
        split_bf16(v.z, h2, l2); split_bf16(v.w, h3, l3);

        __nv_bfloat16* base = g_B + (size_t)row * KX + c * 64 + w;
        __nv_bfloat162* hd = reinterpret_cast<__nv_bfloat162*>(base);
        __nv_bfloat162* ld = reinterpret_cast<__nv_bfloat162*>(base + 32);
        hd[0] = __nv_bfloat162(h0, h1); hd[1] = __nv_bfloat162(h2, h3);
        ld[0] = __nv_bfloat162(l0, l1); ld[1] = __nv_bfloat162(l2, l3);
    }
}

// ---------------------------------------------------------------------------
// Kernel 2: persistent-CTA TMA-pipelined HMMA GEMM (3-term bf16 split)
// Pipeline rolls continuously across output tiles; epilogue overlaps TMA.
// ---------------------------------------------------------------------------
__device__ __forceinline__ void issue_chunk_load(
    int q, int bid, int s, uint32_t tiles_base, uint32_t mbar,
    const CUtensorMap* mapA, const CUtensorMap* mapB)
{
    const int tile = bid + (q >> 4) * GRID_P;
    const int c    = q & 15;
    const int bm   = (tile >> 4) << 7;
    const int bn   = (tile & 15) << 7;
    const uint32_t a_dst = tiles_base + s * STAGE_BYTES;
    const uint32_t b_dst = a_dst + A_TILE_BYTES;
    MBARRIER_EXPECT_TX(mbar, STAGE_BYTES);
    TMA_LOAD_3D(a_dst, mapA, c * 64, bm, 0, mbar);
    TMA_LOAD_3D(b_dst, mapB, c * 64, bn, 0, mbar);
}

__global__ void __launch_bounds__(256, 2) gemm_kernel(
    const __grid_constant__ CUtensorMap tma_a,
    const __grid_constant__ CUtensorMap tma_b,
    const float* __restrict__ bias,
    float* __restrict__ out)
{
    extern __shared__ char dynsmem[];
    __shared__ __align__(8) uint64_t mbar_full[STAGES];

    const int tid  = threadIdx.x;
    const int wid  = tid >> 5;
    const int lane = tid & 31;
    const int bid  = blockIdx.x;

    const int wm = (wid >> 2) * 64;   // warp m offset (0 or 64)
    const int wn = (wid & 3) * 32;    // warp n offset (0,32,64,96)

    const int T = (NTILES - bid + GRID_P - 1) / GRID_P;   // tiles for this CTA
    const int Q = T << 4;                                  // chunks total

    const uint32_t tiles_base = (smem_u32(dynsmem) + 1023u) & ~1023u;

    if (tid == 0) {
        #pragma unroll
        for (int s = 0; s < STAGES; s++)
            MBARRIER_INIT(smem_u32(&mbar_full[s]), 1);
    }
    __syncthreads();

    if (tid == 0) {
        #pragma unroll
        for (int s = 0; s < STAGES; s++)
            issue_chunk_load(s, bid, s, tiles_base, smem_u32(&mbar_full[s]), &tma_a, &tma_b);
    }

    // --- per-lane ldmatrix address components (SW128 swizzle, 128B rows) ---
    const int a_row = wm + ((lane >> 3) & 1) * 8 + (lane & 7);
    const uint32_t a_row_off = (uint32_t)a_row * 128u;
    const uint32_t a_xor = (uint32_t)(a_row & 7) * 16u;
    const uint32_t a_kb = (uint32_t)(lane >> 4) * 16u;
    const int b_row = wn + (lane >> 4) * 8 + (lane & 7);
    const uint32_t b_row_off = (uint32_t)b_row * 128u;
    const uint32_t b_xor = (uint32_t)(b_row & 7) * 16u;
    const uint32_t b_kb = (uint32_t)((lane >> 3) & 1) * 16u;

    const int gr = lane >> 2;
    const int gc = (lane & 3) * 2;

    float acc[4][4][4];
    #pragma unroll
    for (int i = 0; i < 4; i++)
        #pragma unroll
        for (int j = 0; j < 4; j++)
            #pragma unroll
            for (int q2 = 0; q2 < 4; q2++) acc[i][j][q2] = 0.0f;

    int s = 0, par = 0;
    for (int q = 0; q < Q; q++) {
        MBARRIER_WAIT_PARITY(smem_u32(&mbar_full[s]), par);

        const uint32_t a_base = tiles_base + s * STAGE_BYTES + a_row_off;
        const uint32_t b_base = tiles_base + s * STAGE_BYTES + A_TILE_BYTES + b_row_off;

        // 128B row: hi bytes [0,64), lo bytes [64,128); ks picks 32B
        #pragma unroll
        for (int ks = 0; ks < 2; ks++) {
            const uint32_t akh = (uint32_t)ks * 32u + a_kb;
            const uint32_t akl = akh + 64u;
            const uint32_t bkh = (uint32_t)ks * 32u + b_kb;
            const uint32_t bkl = bkh + 64u;

            uint32_t ah[4][4], al[4][4], bh[2][4], bl[2][4];
            #pragma unroll
            for (int mt = 0; mt < 4; mt++)
                LDSM_X4(ah[mt], a_base + (uint32_t)mt * 2048u + (akh ^ a_xor));
            #pragma unroll
            for (int np = 0; np < 2; np++) {
                LDSM_X4(bh[np], b_base + (uint32_t)np * 2048u + (bkh ^ b_xor));
                LDSM_X4(bl[np], b_base + (uint32_t)np * 2048u + (bkl ^ b_xor));
            }
            #pragma unroll
            for (int mt = 0; mt < 4; mt++)
                LDSM_X4(al[mt], a_base + (uint32_t)mt * 2048u + (akl ^ a_xor));

            if (ks == 1) {
                __syncthreads();   // all reads of stage s done -> refill for q+3
                if (tid == 0 && q + STAGES < Q)
                    issue_chunk_load(q + STAGES, bid, s, tiles_base,
                                     smem_u32(&mbar_full[s]), &tma_a, &tma_b);
            }

            #pragma unroll
            for (int mt = 0; mt < 4; mt++)
                #pragma unroll
                for (int nt = 0; nt < 4; nt++)
                    mma16816(acc[mt][nt], ah[mt], &bh[nt >> 1][(nt & 1) * 2]);
            #pragma unroll
            for (int mt = 0; mt < 4; mt++)
                #pragma unroll
                for (int nt = 0; nt < 4; nt++)
                    mma16816(acc[mt][nt], ah[mt], &bl[nt >> 1][(nt & 1) * 2]);
            #pragma unroll
            for (int mt = 0; mt < 4; mt++)
                #pragma unroll
                for (int nt = 0; nt < 4; nt++)
                    mma16816(acc[mt][nt], al[mt], &bh[nt >> 1][(nt & 1) * 2]);
        }

        // advance ring
        if (++s == STAGES) { s = 0; par ^= 1; }

        // --- tile boundary: epilogue (overlaps in-flight TMA of next tile) ---
        if ((q & 15) == 15) {
            const int tile = bid + (q >> 4) * GRID_P;
            const int bm = (tile >> 4) << 7;
            const int bn = (tile & 15) << 7;

            #pragma unroll
            for (int nt = 0; nt < 4; nt++) {
                const int n = bn + wn + nt * 8 + gc;
                const float2 b2 = __ldg(reinterpret_cast<const float2*>(bias + n));
                #pragma unroll
                for (int mt = 0; mt < 4; mt++) {
                    const int m0 = bm + wm + mt * 16 + gr;
                    float v0 = acc[mt][nt][0] + b2.x;
                    float v1 = acc[mt][nt][1] + b2.y;
                    float v2 = acc[mt][nt][2] + b2.x;
                    float v3 = acc[mt][nt][3] + b2.y;
                    float2 o0, o1;
                    o0.x = 0.5f * v0 * (1.0f + erff(v0 * 0.70710678118654752f));
                    o0.y = 0.5f * v1 * (1.0f + erff(v1 * 0.70710678118654752f));
                    o1.x = 0.5f * v2 * (1.0f + erff(v2 * 0.70710678118654752f));
                    o1.y = 0.5f * v3 * (1.0f + erff(v3 * 0.70710678118654752f));
                    *reinterpret_cast<float2*>(out + (size_t)m0 * N_DIM + n) = o0;
                    *reinterpret_cast<float2*>(out + (size_t)(m0 + 8) * N_DIM + n) = o1;
                    acc[mt][nt][0] = 0.0f; acc[mt][nt][1] = 0.0f;
                    acc[mt][nt][2] = 0.0f; acc[mt][nt][3] = 0.0f;
                }
            }
        }
    }
}

// ---------------------------------------------------------------------------
// Host side
// ---------------------------------------------------------------------------
typedef CUresult (*EncodeFn)(CUtensorMap*, CUtensorMapDataType, cuuint32_t, void*,
                             const cuuint64_t*, const cuuint64_t*, const cuuint32_t*,
                             const cuuint32_t*, CUtensorMapInterleave, CUtensorMapSwizzle,
                             CUtensorMapL2promotion, CUtensorMapFloatOOBfill);

static void encode_map(EncodeFn enc, CUtensorMap* map, void* base, uint64_t rows) {
    uint64_t dims[3]    = {KX, rows, 1};
    uint64_t strides[2] = {KX * sizeof(__nv_bfloat16), rows * KX * sizeof(__nv_bfloat16)};
    uint32_t box[3]     = {64, 128, 1};
    uint32_t estr[3]    = {1, 1, 1};
    enc(map, CU_TENSOR_MAP_DATA_TYPE_BFLOAT16, 3, base, dims, strides, box, estr,
        CU_TENSOR_MAP_INTERLEAVE_NONE, CU_TENSOR_MAP_SWIZZLE_128B,
        CU_TENSOR_MAP_L2_PROMOTION_L2_128B, CU_TENSOR_MAP_FLOAT_OOB_FILL_NONE);
}

extern "C" void kernel_launch(void* const* d_in, const int* in_sizes, int n_in,
                              void* d_out, int out_size) {
    const float* x     = (const float*)d_in[0];
    const float* gamma = (const float*)d_in[1];
    const float* beta  = (const float*)d_in[2];
    const float* W     = (const float*)d_in[3];
    const float* b     = (const float*)d_in[4];
    float* out = (float*)d_out;

    void* pA = nullptr; void* pB = nullptr;
    cudaGetSymbolAddress(&pA, g_A);
    cudaGetSymbolAddress(&pB, g_B);

    EncodeFn enc = nullptr;
    cudaDriverEntryPointQueryResult qres;
    cudaGetDriverEntryPoint("cuTensorMapEncodeTiled", (void**)&enc, cudaEnableDefault, &qres);

    CUtensorMap mapA, mapB;
    encode_map(enc, &mapA, pA, M_TOTAL);
    encode_map(enc, &mapB, pB, N_DIM);

    convert_kernel<<<M_TOTAL + N_DIM, 128>>>(x, gamma, beta, W);

    cudaFuncSetAttribute(gemm_kernel, cudaFuncAttributeMaxDynamicSharedMemorySize, SMEM_DYN);
    gemm_kernel<<<GRID_P, 256, SMEM_DYN>>>(mapA, mapB, b, out);
}